// round 7
// baseline (speedup 1.0000x reference)
#include <cuda_runtime.h>
#include <cuda_bf16.h>
#include <cstdint>

#define N_NODES 50000
#define EMBED_DIM 128
#define N_EDGES 500000
#define NBLK ((N_NODES + 255) / 256)   // 196 scan blocks

// Scratch: device globals (no runtime allocation allowed).
__device__ int   g_cnt[N_NODES];
__device__ int   g_bsum[NBLK];
__device__ int   g_rowstart[N_NODES + 1];
__device__ int   g_cursor[N_NODES];
__device__ int   g_col[N_EDGES];
__device__ float g_val[N_EDGES];
__device__ float g_dis[N_NODES];
__device__ float g_agg[N_NODES * EMBED_DIM];
__device__ float g_h[N_NODES * EMBED_DIM];

// ---------------- packed f32x2 helpers ----------------
__device__ __forceinline__ unsigned long long pack2(float lo, float hi) {
    unsigned long long r;
    asm("mov.b64 %0, {%1, %2};" : "=l"(r) : "f"(lo), "f"(hi));
    return r;
}
__device__ __forceinline__ void unpack2(unsigned long long v, float& lo, float& hi) {
    asm("mov.b64 {%0, %1}, %2;" : "=f"(lo), "=f"(hi) : "l"(v));
}
__device__ __forceinline__ unsigned long long fma2(unsigned long long a,
                                                   unsigned long long b,
                                                   unsigned long long c) {
    unsigned long long r;
    asm("fma.rn.f32x2 %0, %1, %2, %3;" : "=l"(r) : "l"(a), "l"(b), "l"(c));
    return r;
}

// ---------------- CSR build ----------------
__global__ void k_zero_cnt() {
    int i = blockIdx.x * blockDim.x + threadIdx.x;
    if (i < N_NODES) g_cnt[i] = 0;
}
__global__ void k_hist(const int* __restrict__ ei) {
    int e = blockIdx.x * blockDim.x + threadIdx.x;
    if (e < N_EDGES) {
        unsigned d = (unsigned)ei[N_EDGES + e];
        if (d < N_NODES) atomicAdd(&g_cnt[d], 1);
    }
}
__global__ __launch_bounds__(256) void k_blocksum() {
    __shared__ int sh[256];
    int t = threadIdx.x;
    int i = blockIdx.x * 256 + t;
    sh[t] = (i < N_NODES) ? g_cnt[i] : 0;
    __syncthreads();
    #pragma unroll
    for (int off = 128; off > 0; off >>= 1) {
        if (t < off) sh[t] += sh[t + off];
        __syncthreads();
    }
    if (t == 0) g_bsum[blockIdx.x] = sh[0];
}
// merged: each block reduces bsum[0..bid) itself (NBLK=196 < 256), then local scan
__global__ __launch_bounds__(256) void k_scan_final() {
    __shared__ int red[256];
    __shared__ int sh[256];
    int t = threadIdx.x;
    int i = blockIdx.x * 256 + t;
    red[t] = (t < blockIdx.x) ? g_bsum[t] : 0;
    __syncthreads();
    #pragma unroll
    for (int off = 128; off > 0; off >>= 1) {
        if (t < off) red[t] += red[t + off];
        __syncthreads();
    }
    int blockoff = red[0];
    int v = (i < N_NODES) ? g_cnt[i] : 0;
    sh[t] = v;
    __syncthreads();
    #pragma unroll
    for (int off = 1; off < 256; off <<= 1) {
        int add = (t >= off) ? sh[t - off] : 0;
        __syncthreads();
        sh[t] += add;
        __syncthreads();
    }
    if (i < N_NODES) {
        int rs = blockoff + sh[t] - v;   // exclusive
        g_rowstart[i] = rs;
        g_cursor[i]   = rs;
        g_dis[i]      = rsqrtf((float)(v + 1));
    }
    if (i == 0) g_rowstart[N_NODES] = N_EDGES;
}
__global__ void k_fill(const int* __restrict__ ei) {
    int e = blockIdx.x * blockDim.x + threadIdx.x;
    if (e >= N_EDGES) return;
    unsigned s = (unsigned)ei[e];
    unsigned d = (unsigned)ei[N_EDGES + e];
    if (s >= N_NODES || d >= N_NODES) return;
    int pos = atomicAdd(&g_cursor[d], 1);
    g_col[pos] = s;
    g_val[pos] = g_dis[s] * g_dis[d];
}

// ---------------- gather-aggregate (warp per node) ----------------
// Also optionally writes raw input row to out2 (identity init_embeds copy).
__global__ __launch_bounds__(256) void k_gather(const float* __restrict__ x, int use_h,
                                                float* __restrict__ out2) {
    int idx = blockIdx.x * blockDim.x + threadIdx.x;
    int node = idx >> 5;
    if (node >= N_NODES) return;
    const float* in = use_h ? g_h : x;
    int lane = idx & 31;

    float di = g_dis[node];
    float c = di * di;
    float4 raw = ((const float4*)(in + (size_t)node * EMBED_DIM))[lane];
    if (out2) ((float4*)(out2 + (size_t)node * EMBED_DIM))[lane] = raw;
    float4 acc;
    acc.x = raw.x * c; acc.y = raw.y * c; acc.z = raw.z * c; acc.w = raw.w * c;

    int j   = g_rowstart[node];
    int end = g_rowstart[node + 1];
    for (; j + 2 <= end; j += 2) {
        int   s0 = g_col[j],     s1 = g_col[j + 1];
        float n0 = g_val[j],     n1 = g_val[j + 1];
        float4 v0 = ((const float4*)(in + (size_t)s0 * EMBED_DIM))[lane];
        float4 v1 = ((const float4*)(in + (size_t)s1 * EMBED_DIM))[lane];
        acc.x += n0 * v0.x + n1 * v1.x;
        acc.y += n0 * v0.y + n1 * v1.y;
        acc.z += n0 * v0.z + n1 * v1.z;
        acc.w += n0 * v0.w + n1 * v1.w;
    }
    if (j < end) {
        int   s0 = g_col[j];
        float n0 = g_val[j];
        float4 v0 = ((const float4*)(in + (size_t)s0 * EMBED_DIM))[lane];
        acc.x += n0 * v0.x; acc.y += n0 * v0.y;
        acc.z += n0 * v0.z; acc.w += n0 * v0.w;
    }
    ((float4*)(g_agg + (size_t)node * EMBED_DIM))[lane] = acc;
}

// ---------------- GEMM + bias + tanh, packed f32x2 ----------------
// 64 rows/block, 256 threads. Warp w: rows w*8..w*8+7; lane: cols lane*4..+3
// A tile staged in shared as DUPLICATED pairs {a,a} so LDS.64 gives the packed
// broadcast operand directly (no per-iteration MOV packs for A).
#define GEMM_SMEM (64 * 128 * sizeof(float2))   // 64KB

__global__ __launch_bounds__(256) void k_gemm_bias_tanh(
    const float* __restrict__ W, const float* __restrict__ b,
    float* __restrict__ out, int to_h)
{
    extern __shared__ float2 As2[];   // [64][128]
    float* dst = to_h ? g_h : out;
    int row0 = blockIdx.x * 64;
    int tid = threadIdx.x;

    // Stage A tile: duplicated pairs. Coalesced global reads.
    #pragma unroll
    for (int i = 0; i < 32; i++) {
        int idx = tid + i * 256;
        int r = idx >> 7, k = idx & 127;
        int gr = row0 + r;
        float a = (gr < N_NODES) ? g_agg[(size_t)gr * EMBED_DIM + k] : 0.0f;
        As2[r * 128 + k] = make_float2(a, a);
    }
    __syncthreads();

    int warp = tid >> 5, lane = tid & 31;
    int r0 = warp * 8;
    int c0 = lane * 4;

    unsigned long long acc2[8][2];
    unsigned long long z = pack2(0.0f, 0.0f);
    #pragma unroll
    for (int j = 0; j < 8; j++) { acc2[j][0] = z; acc2[j][1] = z; }

    const unsigned long long* As2u = (const unsigned long long*)As2;

    #pragma unroll 8
    for (int k = 0; k < EMBED_DIM; k++) {
        float4 w = *(const float4*)(W + (size_t)k * EMBED_DIM + c0);
        unsigned long long w01 = pack2(w.x, w.y);
        unsigned long long w23 = pack2(w.z, w.w);
        #pragma unroll
        for (int j = 0; j < 8; j++) {
            unsigned long long aa = As2u[(r0 + j) * 128 + k];  // LDS.64 broadcast
            acc2[j][0] = fma2(aa, w01, acc2[j][0]);
            acc2[j][1] = fma2(aa, w23, acc2[j][1]);
        }
    }

    float4 bb = *(const float4*)(b + c0);
    #pragma unroll
    for (int j = 0; j < 8; j++) {
        int gr = row0 + r0 + j;
        if (gr < N_NODES) {
            float a0, a1, a2, a3;
            unpack2(acc2[j][0], a0, a1);
            unpack2(acc2[j][1], a2, a3);
            float4 o;
            o.x = tanhf(a0 + bb.x);
            o.y = tanhf(a1 + bb.y);
            o.z = tanhf(a2 + bb.z);
            o.w = tanhf(a3 + bb.w);
            *(float4*)(dst + (size_t)gr * EMBED_DIM + c0) = o;
        }
    }
}

extern "C" void kernel_launch(void* const* d_in, const int* in_sizes, int n_in,
                              void* d_out, int out_size) {
    const float* x  = (const float*)d_in[0];
    const int*   ei = (const int*)d_in[1];
    const float* W1 = (const float*)d_in[2];
    const float* b1 = (const float*)d_in[3];
    const float* W2 = (const float*)d_in[4];
    const float* b2 = (const float*)d_in[5];
    float* out = (float*)d_out;

    cudaFuncSetAttribute(k_gemm_bias_tanh,
                         cudaFuncAttributeMaxDynamicSharedMemorySize, GEMM_SMEM);

    const int NT = 256;
    int blksE  = (N_EDGES + NT - 1) / NT;
    int blksND = (N_NODES * 32 + NT - 1) / NT;
    int blksG  = (N_NODES + 63) / 64;

    // CSR build + normalization
    k_zero_cnt<<<NBLK, NT>>>();
    k_hist<<<blksE, NT>>>(ei);
    k_blocksum<<<NBLK, NT>>>();
    k_scan_final<<<NBLK, NT>>>();
    k_fill<<<blksE, NT>>>(ei);

    float* out2 = (out_size >= 2 * N_NODES * EMBED_DIM)
                ? out + (size_t)N_NODES * EMBED_DIM : nullptr;

    // layer 1 (gather also writes the identity copy of x)
    k_gather<<<blksND, NT>>>(x, 0, out2);
    k_gemm_bias_tanh<<<blksG, NT, GEMM_SMEM>>>(W1, b1, out, 1);

    // layer 2
    k_gather<<<blksND, NT>>>(x, 1, nullptr);
    k_gemm_bias_tanh<<<blksG, NT, GEMM_SMEM>>>(W2, b2, out, 0);
}

// round 8
// speedup vs baseline: 1.5832x; 1.5832x over previous
#include <cuda_runtime.h>
#include <cuda_bf16.h>
#include <cstdint>

#define N_NODES 50000
#define EMBED_DIM 128
#define N_EDGES 500000
#define NBLK ((N_NODES + 255) / 256)   // 196

// ---------------- device scratch ----------------
__device__ int   g_cnt[N_NODES];
__device__ int   g_bsum[NBLK];
__device__ int   g_rowstart[N_NODES + 1];
__device__ int   g_cursor[N_NODES];
__device__ int   g_col[N_EDGES];
__device__ float g_val[N_EDGES];
__device__ float g_dis[N_NODES];
__device__ float g_agg[N_NODES * EMBED_DIM];
__device__ float g_h[N_NODES * EMBED_DIM];
// W split images, stored transposed: Bh[layer][n*128+k] = bf16_hi(W[k][n])
__device__ __nv_bfloat16 g_Bh[2][128 * 128];
__device__ __nv_bfloat16 g_Bl[2][128 * 128];

// ---------------- CSR build ----------------
__global__ void k_zero_cnt() {
    int i = blockIdx.x * blockDim.x + threadIdx.x;
    if (i < N_NODES) g_cnt[i] = 0;
}
__global__ void k_hist(const int* __restrict__ ei) {
    int e = blockIdx.x * blockDim.x + threadIdx.x;
    if (e < N_EDGES) {
        unsigned d = (unsigned)ei[N_EDGES + e];
        if (d < N_NODES) atomicAdd(&g_cnt[d], 1);
    }
}
__global__ __launch_bounds__(256) void k_blocksum() {
    __shared__ int sh[256];
    int t = threadIdx.x;
    int i = blockIdx.x * 256 + t;
    sh[t] = (i < N_NODES) ? g_cnt[i] : 0;
    __syncthreads();
    #pragma unroll
    for (int off = 128; off > 0; off >>= 1) {
        if (t < off) sh[t] += sh[t + off];
        __syncthreads();
    }
    if (t == 0) g_bsum[blockIdx.x] = sh[0];
}
__global__ __launch_bounds__(256) void k_scan_final() {
    __shared__ int red[256];
    __shared__ int sh[256];
    int t = threadIdx.x;
    int i = blockIdx.x * 256 + t;
    red[t] = (t < blockIdx.x) ? g_bsum[t] : 0;
    __syncthreads();
    #pragma unroll
    for (int off = 128; off > 0; off >>= 1) {
        if (t < off) red[t] += red[t + off];
        __syncthreads();
    }
    int blockoff = red[0];
    int v = (i < N_NODES) ? g_cnt[i] : 0;
    sh[t] = v;
    __syncthreads();
    #pragma unroll
    for (int off = 1; off < 256; off <<= 1) {
        int add = (t >= off) ? sh[t - off] : 0;
        __syncthreads();
        sh[t] += add;
        __syncthreads();
    }
    if (i < N_NODES) {
        int rs = blockoff + sh[t] - v;
        g_rowstart[i] = rs;
        g_cursor[i]   = rs;
        g_dis[i]      = rsqrtf((float)(v + 1));
    }
    if (i == 0) g_rowstart[N_NODES] = N_EDGES;
}
__global__ void k_fill(const int* __restrict__ ei) {
    int e = blockIdx.x * blockDim.x + threadIdx.x;
    if (e >= N_EDGES) return;
    unsigned s = (unsigned)ei[e];
    unsigned d = (unsigned)ei[N_EDGES + e];
    if (s >= N_NODES || d >= N_NODES) return;
    int pos = atomicAdd(&g_cursor[d], 1);
    g_col[pos] = s;
    g_val[pos] = g_dis[s] * g_dis[d];
}

// ---------------- weight prep: split + transpose ----------------
__global__ void k_prep_B(const float* __restrict__ W1, const float* __restrict__ W2) {
    int idx = blockIdx.x * blockDim.x + threadIdx.x;
    if (idx >= 2 * 128 * 128) return;
    int layer = idx >> 14;
    int e = idx & 16383;
    int k = e >> 7, n = e & 127;            // coalesced read of W[k][n]
    const float* W = layer ? W2 : W1;
    float w = W[k * 128 + n];
    __nv_bfloat16 wh = __float2bfloat16(w);
    __nv_bfloat16 wl = __float2bfloat16(w - __bfloat162float(wh));
    g_Bh[layer][n * 128 + k] = wh;          // transposed: row n, col k
    g_Bl[layer][n * 128 + k] = wl;
}

// ---------------- gather-aggregate (warp per node) ----------------
__global__ __launch_bounds__(256) void k_gather(const float* __restrict__ x, int use_h,
                                                float* __restrict__ out2) {
    int idx = blockIdx.x * blockDim.x + threadIdx.x;
    int node = idx >> 5;
    if (node >= N_NODES) return;
    const float* in = use_h ? g_h : x;
    int lane = idx & 31;

    float di = g_dis[node];
    float c = di * di;
    float4 raw = ((const float4*)(in + (size_t)node * EMBED_DIM))[lane];
    if (out2) ((float4*)(out2 + (size_t)node * EMBED_DIM))[lane] = raw;
    float4 acc;
    acc.x = raw.x * c; acc.y = raw.y * c; acc.z = raw.z * c; acc.w = raw.w * c;

    int j   = g_rowstart[node];
    int end = g_rowstart[node + 1];
    for (; j + 2 <= end; j += 2) {
        int   s0 = g_col[j],     s1 = g_col[j + 1];
        float n0 = g_val[j],     n1 = g_val[j + 1];
        float4 v0 = ((const float4*)(in + (size_t)s0 * EMBED_DIM))[lane];
        float4 v1 = ((const float4*)(in + (size_t)s1 * EMBED_DIM))[lane];
        acc.x += n0 * v0.x + n1 * v1.x;
        acc.y += n0 * v0.y + n1 * v1.y;
        acc.z += n0 * v0.z + n1 * v1.z;
        acc.w += n0 * v0.w + n1 * v1.w;
    }
    if (j < end) {
        int   s0 = g_col[j];
        float n0 = g_val[j];
        float4 v0 = ((const float4*)(in + (size_t)s0 * EMBED_DIM))[lane];
        acc.x += n0 * v0.x; acc.y += n0 * v0.y;
        acc.z += n0 * v0.z; acc.w += n0 * v0.w;
    }
    ((float4*)(g_agg + (size_t)node * EMBED_DIM))[lane] = acc;
}

// ---------------- HMMA bf16x3 GEMM + bias + tanh ----------------
// Tile: 64 rows x 128 cols per CTA, K=128. 8 warps.
// Warp w: rows m0=(w&3)*16 .. +15, cols n_base=(w>>2)*64 .. +63 (8 n8-tiles).
// smem: padded rows of 136 bf16 (272B) -> conflict-free ldmatrix.
#define PAD 136
#define A_IMG (64 * PAD * 2)     // 17408 B
#define B_IMG (128 * PAD * 2)    // 34816 B
#define SM_AH 0
#define SM_AL A_IMG
#define SM_BH (2 * A_IMG)
#define SM_BL (2 * A_IMG + B_IMG)
#define MMA_SMEM (2 * A_IMG + 2 * B_IMG)   // 104448 B

__device__ __forceinline__ uint32_t smem_u32(const void* p) {
    uint32_t a;
    asm("{ .reg .u64 t; cvta.to.shared.u64 t, %1; cvt.u32.u64 %0, t; }" : "=r"(a) : "l"(p));
    return a;
}
__device__ __forceinline__ void ldm_x4(uint32_t* r, uint32_t addr) {
    asm volatile("ldmatrix.sync.aligned.m8n8.x4.shared.b16 {%0,%1,%2,%3}, [%4];"
                 : "=r"(r[0]), "=r"(r[1]), "=r"(r[2]), "=r"(r[3]) : "r"(addr));
}
__device__ __forceinline__ void mma_bf16(float* d, const uint32_t* a, uint32_t b0, uint32_t b1) {
    asm volatile(
        "mma.sync.aligned.m16n8k16.row.col.f32.bf16.bf16.f32 "
        "{%0,%1,%2,%3}, {%4,%5,%6,%7}, {%8,%9}, {%0,%1,%2,%3};"
        : "+f"(d[0]), "+f"(d[1]), "+f"(d[2]), "+f"(d[3])
        : "r"(a[0]), "r"(a[1]), "r"(a[2]), "r"(a[3]), "r"(b0), "r"(b1));
}

__global__ __launch_bounds__(256) void k_mma_gemm(const float* __restrict__ bvec,
                                                  float* __restrict__ out,
                                                  int layer, int to_h) {
    extern __shared__ char sm[];
    __nv_bfloat16* sAH = (__nv_bfloat16*)(sm + SM_AH);
    __nv_bfloat16* sAL = (__nv_bfloat16*)(sm + SM_AL);
    int tid = threadIdx.x, wid = tid >> 5, lane = tid & 31;
    int row0 = blockIdx.x * 64;
    float* dst = to_h ? g_h : out;

    // stage B images: 128 rows x 128 bf16 -> padded rows (uint4 = 8 bf16)
    {
        const uint4* bh = (const uint4*)g_Bh[layer];
        const uint4* bl = (const uint4*)g_Bl[layer];
        #pragma unroll
        for (int i = 0; i < 8; i++) {
            int idx = tid + i * 256;          // 0..2047
            int n = idx >> 4, c = idx & 15;
            *(uint4*)(sm + SM_BH + n * (PAD * 2) + c * 16) = bh[idx];
            *(uint4*)(sm + SM_BL + n * (PAD * 2) + c * 16) = bl[idx];
        }
    }
    // stage A: split f32 -> bf16 hi/lo
    #pragma unroll
    for (int i = 0; i < 32; i++) {
        int idx = tid + i * 256;              // 0..8191
        int r = idx >> 7, k = idx & 127;
        int gr = row0 + r;
        float a = (gr < N_NODES) ? g_agg[(size_t)gr * EMBED_DIM + k] : 0.0f;
        __nv_bfloat16 ah = __float2bfloat16(a);
        __nv_bfloat16 al = __float2bfloat16(a - __bfloat162float(ah));
        sAH[r * PAD + k] = ah;
        sAL[r * PAD + k] = al;
    }
    __syncthreads();

    int m0 = (wid & 3) * 16;
    int n_base = (wid >> 2) * 64;

    // ldmatrix lane addresses
    uint32_t sb = smem_u32(sm);
    // A: row = m0 + (lane&15), k byte off = (lane&16)
    uint32_t aoff = (uint32_t)((m0 + (lane & 15)) * (PAD * 2) + (lane & 16));
    uint32_t aAddrH = sb + SM_AH + aoff;
    uint32_t aAddrL = sb + SM_AL + aoff;
    // B pair p (16 n-rows): n = n0 + (lane&7) + ((lane>>1)&8), k byte off = (lane&8)*2
    uint32_t bAddrH[4], bAddrL[4];
    #pragma unroll
    for (int p = 0; p < 4; p++) {
        int n = n_base + p * 16 + (lane & 7) + ((lane >> 1) & 8);
        uint32_t boff = (uint32_t)(n * (PAD * 2) + (lane & 8) * 2);
        bAddrH[p] = sb + SM_BH + boff;
        bAddrL[p] = sb + SM_BL + boff;
    }

    float d[8][4];
    #pragma unroll
    for (int t = 0; t < 8; t++)
        #pragma unroll
        for (int q = 0; q < 4; q++) d[t][q] = 0.0f;

    #pragma unroll
    for (int kk = 0; kk < 8; kk++) {
        uint32_t kb = kk * 32;   // 16 bf16 = 32 bytes
        uint32_t ah[4], al[4], bh[4][4], bl[4][4];
        ldm_x4(ah, aAddrH + kb);
        ldm_x4(al, aAddrL + kb);
        #pragma unroll
        for (int p = 0; p < 4; p++) {
            ldm_x4(bh[p], bAddrH[p] + kb);
            ldm_x4(bl[p], bAddrL[p] + kb);
        }
        #pragma unroll
        for (int p = 0; p < 4; p++) {
            #pragma unroll
            for (int q = 0; q < 2; q++) {
                int t = p * 2 + q;
                mma_bf16(d[t], ah, bh[p][2 * q], bh[p][2 * q + 1]);   // Ah*Bh
                mma_bf16(d[t], ah, bl[p][2 * q], bl[p][2 * q + 1]);   // Ah*Bl
                mma_bf16(d[t], al, bh[p][2 * q], bh[p][2 * q + 1]);   // Al*Bh
            }
        }
    }

    // epilogue: thread holds rows (m0+g, m0+g+8), cols n0+2c..+1 per tile
    int g = lane >> 2;
    int c2 = (lane & 3) * 2;
    int rowA = row0 + m0 + g;
    int rowB = rowA + 8;
    #pragma unroll
    for (int t = 0; t < 8; t++) {
        int col = n_base + t * 8 + c2;
        float bx = bvec[col], by = bvec[col + 1];
        if (rowA < N_NODES) {
            float2 o;
            o.x = tanhf(d[t][0] + bx);
            o.y = tanhf(d[t][1] + by);
            *(float2*)(dst + (size_t)rowA * EMBED_DIM + col) = o;
        }
        if (rowB < N_NODES) {
            float2 o;
            o.x = tanhf(d[t][2] + bx);
            o.y = tanhf(d[t][3] + by);
            *(float2*)(dst + (size_t)rowB * EMBED_DIM + col) = o;
        }
    }
}

extern "C" void kernel_launch(void* const* d_in, const int* in_sizes, int n_in,
                              void* d_out, int out_size) {
    const float* x  = (const float*)d_in[0];
    const int*   ei = (const int*)d_in[1];
    const float* W1 = (const float*)d_in[2];
    const float* b1 = (const float*)d_in[3];
    const float* W2 = (const float*)d_in[4];
    const float* b2 = (const float*)d_in[5];
    float* out = (float*)d_out;

    cudaFuncSetAttribute(k_mma_gemm,
                         cudaFuncAttributeMaxDynamicSharedMemorySize, MMA_SMEM);

    const int NT = 256;
    int blksE  = (N_EDGES + NT - 1) / NT;
    int blksND = (N_NODES * 32 + NT - 1) / NT;
    int blksG  = (N_NODES + 63) / 64;   // 782

    // CSR build + normalization
    k_zero_cnt<<<NBLK, NT>>>();
    k_hist<<<blksE, NT>>>(ei);
    k_blocksum<<<NBLK, NT>>>();
    k_scan_final<<<NBLK, NT>>>();
    k_fill<<<blksE, NT>>>(ei);

    // weight split/transpose
    k_prep_B<<<128, NT>>>(W1, W2);

    float* out2 = (out_size >= 2 * N_NODES * EMBED_DIM)
                ? out + (size_t)N_NODES * EMBED_DIM : nullptr;

    // layer 1 (gather also writes the identity copy of x)
    k_gather<<<blksND, NT>>>(x, 0, out2);
    k_mma_gemm<<<blksG, NT, MMA_SMEM>>>(b1, out, 0, 1);

    // layer 2
    k_gather<<<blksND, NT>>>(x, 1, nullptr);
    k_mma_gemm<<<blksG, NT, MMA_SMEM>>>(b2, out, 1, 0);
}

// round 9
// speedup vs baseline: 1.6765x; 1.0589x over previous
#include <cuda_runtime.h>
#include <cuda_bf16.h>
#include <cstdint>

#define N_NODES 50000
#define EMBED_DIM 128
#define N_EDGES 500000
#define NBLK ((N_NODES + 255) / 256)   // 196

// ---------------- device scratch (zero-initialized at module load) ----------------
__device__ int   g_cnt[N_NODES];          // self-cleaning histogram
__device__ int   g_bsum[NBLK];
__device__ int   g_rowstart[N_NODES + 1];
__device__ int   g_cursor[N_NODES];
__device__ unsigned long long g_edge[N_EDGES];   // packed {val_f32<<32 | col}
__device__ float g_dis[N_NODES];
__device__ float g_agg[N_NODES * EMBED_DIM];
__device__ float g_h[N_NODES * EMBED_DIM];
// W split images, transposed: Bh[layer][n*128+k] = bf16_hi(W[k][n])
__device__ __nv_bfloat16 g_Bh[2][128 * 128];
__device__ __nv_bfloat16 g_Bl[2][128 * 128];

// ---------------- hist (+ fused weight prep) ----------------
__global__ void k_hist(const int* __restrict__ ei,
                       const float* __restrict__ W1, const float* __restrict__ W2) {
    int e = blockIdx.x * blockDim.x + threadIdx.x;
    if (e < N_EDGES) {
        unsigned d = (unsigned)ei[N_EDGES + e];
        if (d < N_NODES) atomicAdd(&g_cnt[d], 1);
    }
    // dual-duty: first 128 blocks also split/transpose the weights (32768 elems)
    if (blockIdx.x < 128) {
        int idx = blockIdx.x * blockDim.x + threadIdx.x;   // 0..32767
        int layer = idx >> 14;
        int t = idx & 16383;
        int k = t >> 7, n = t & 127;
        const float* W = layer ? W2 : W1;
        float w = W[k * 128 + n];
        __nv_bfloat16 wh = __float2bfloat16(w);
        __nv_bfloat16 wl = __float2bfloat16(w - __bfloat162float(wh));
        g_Bh[layer][n * 128 + k] = wh;
        g_Bl[layer][n * 128 + k] = wl;
    }
}

__global__ __launch_bounds__(256) void k_blocksum() {
    __shared__ int sh[256];
    int t = threadIdx.x;
    int i = blockIdx.x * 256 + t;
    sh[t] = (i < N_NODES) ? g_cnt[i] : 0;
    __syncthreads();
    #pragma unroll
    for (int off = 128; off > 0; off >>= 1) {
        if (t < off) sh[t] += sh[t + off];
        __syncthreads();
    }
    if (t == 0) g_bsum[blockIdx.x] = sh[0];
}

// per-block: reduce bsum[0..bid), local scan, emit rowstart/cursor/dis; zero cnt
__global__ __launch_bounds__(256) void k_scan_final() {
    __shared__ int red[256];
    __shared__ int sh[256];
    int t = threadIdx.x;
    int i = blockIdx.x * 256 + t;
    red[t] = (t < blockIdx.x) ? g_bsum[t] : 0;
    __syncthreads();
    #pragma unroll
    for (int off = 128; off > 0; off >>= 1) {
        if (t < off) red[t] += red[t + off];
        __syncthreads();
    }
    int blockoff = red[0];
    int v = (i < N_NODES) ? g_cnt[i] : 0;
    sh[t] = v;
    __syncthreads();
    #pragma unroll
    for (int off = 1; off < 256; off <<= 1) {
        int add = (t >= off) ? sh[t - off] : 0;
        __syncthreads();
        sh[t] += add;
        __syncthreads();
    }
    if (i < N_NODES) {
        int rs = blockoff + sh[t] - v;
        g_rowstart[i] = rs;
        g_cursor[i]   = rs;
        g_dis[i]      = rsqrtf((float)(v + 1));
        g_cnt[i]      = 0;                 // self-clean for next replay
    }
    if (i == 0) g_rowstart[N_NODES] = N_EDGES;
}

__global__ void k_fill(const int* __restrict__ ei) {
    int e = blockIdx.x * blockDim.x + threadIdx.x;
    if (e >= N_EDGES) return;
    unsigned s = (unsigned)ei[e];
    unsigned d = (unsigned)ei[N_EDGES + e];
    if (s >= N_NODES || d >= N_NODES) return;
    int pos = atomicAdd(&g_cursor[d], 1);
    float nm = g_dis[s] * g_dis[d];
    g_edge[pos] = ((unsigned long long)__float_as_uint(nm) << 32) | (unsigned long long)s;
}

// ---------------- gather-aggregate (warp per node, unroll 4) ----------------
__global__ __launch_bounds__(256) void k_gather(const float* __restrict__ x, int use_h,
                                                float* __restrict__ out2) {
    int idx = blockIdx.x * blockDim.x + threadIdx.x;
    int node = idx >> 5;
    if (node >= N_NODES) return;
    const float* in = use_h ? g_h : x;
    int lane = idx & 31;

    float di = g_dis[node];
    float c = di * di;
    float4 raw = ((const float4*)(in + (size_t)node * EMBED_DIM))[lane];
    if (out2) ((float4*)(out2 + (size_t)node * EMBED_DIM))[lane] = raw;
    float4 acc;
    acc.x = raw.x * c; acc.y = raw.y * c; acc.z = raw.z * c; acc.w = raw.w * c;

    int j   = g_rowstart[node];
    int end = g_rowstart[node + 1];

    for (; j + 4 <= end; j += 4) {
        unsigned long long p0 = g_edge[j],     p1 = g_edge[j + 1];
        unsigned long long p2 = g_edge[j + 2], p3 = g_edge[j + 3];
        int s0 = (int)(unsigned)p0, s1 = (int)(unsigned)p1;
        int s2 = (int)(unsigned)p2, s3 = (int)(unsigned)p3;
        float n0 = __uint_as_float((unsigned)(p0 >> 32));
        float n1 = __uint_as_float((unsigned)(p1 >> 32));
        float n2 = __uint_as_float((unsigned)(p2 >> 32));
        float n3 = __uint_as_float((unsigned)(p3 >> 32));
        float4 v0 = ((const float4*)(in + (size_t)s0 * EMBED_DIM))[lane];
        float4 v1 = ((const float4*)(in + (size_t)s1 * EMBED_DIM))[lane];
        float4 v2 = ((const float4*)(in + (size_t)s2 * EMBED_DIM))[lane];
        float4 v3 = ((const float4*)(in + (size_t)s3 * EMBED_DIM))[lane];
        acc.x += n0 * v0.x + n1 * v1.x + n2 * v2.x + n3 * v3.x;
        acc.y += n0 * v0.y + n1 * v1.y + n2 * v2.y + n3 * v3.y;
        acc.z += n0 * v0.z + n1 * v1.z + n2 * v2.z + n3 * v3.z;
        acc.w += n0 * v0.w + n1 * v1.w + n2 * v2.w + n3 * v3.w;
    }
    for (; j < end; j++) {
        unsigned long long p0 = g_edge[j];
        int s0 = (int)(unsigned)p0;
        float n0 = __uint_as_float((unsigned)(p0 >> 32));
        float4 v0 = ((const float4*)(in + (size_t)s0 * EMBED_DIM))[lane];
        acc.x += n0 * v0.x; acc.y += n0 * v0.y;
        acc.z += n0 * v0.z; acc.w += n0 * v0.w;
    }
    ((float4*)(g_agg + (size_t)node * EMBED_DIM))[lane] = acc;
}

// ---------------- HMMA bf16x3 GEMM + bias + tanh (unchanged, proven) ----------------
#define PAD 136
#define A_IMG (64 * PAD * 2)
#define B_IMG (128 * PAD * 2)
#define SM_AH 0
#define SM_AL A_IMG
#define SM_BH (2 * A_IMG)
#define SM_BL (2 * A_IMG + B_IMG)
#define MMA_SMEM (2 * A_IMG + 2 * B_IMG)   // 104448 B

__device__ __forceinline__ uint32_t smem_u32(const void* p) {
    uint32_t a;
    asm("{ .reg .u64 t; cvta.to.shared.u64 t, %1; cvt.u32.u64 %0, t; }" : "=r"(a) : "l"(p));
    return a;
}
__device__ __forceinline__ void ldm_x4(uint32_t* r, uint32_t addr) {
    asm volatile("ldmatrix.sync.aligned.m8n8.x4.shared.b16 {%0,%1,%2,%3}, [%4];"
                 : "=r"(r[0]), "=r"(r[1]), "=r"(r[2]), "=r"(r[3]) : "r"(addr));
}
__device__ __forceinline__ void mma_bf16(float* d, const uint32_t* a, uint32_t b0, uint32_t b1) {
    asm volatile(
        "mma.sync.aligned.m16n8k16.row.col.f32.bf16.bf16.f32 "
        "{%0,%1,%2,%3}, {%4,%5,%6,%7}, {%8,%9}, {%0,%1,%2,%3};"
        : "+f"(d[0]), "+f"(d[1]), "+f"(d[2]), "+f"(d[3])
        : "r"(a[0]), "r"(a[1]), "r"(a[2]), "r"(a[3]), "r"(b0), "r"(b1));
}

__global__ __launch_bounds__(256) void k_mma_gemm(const float* __restrict__ bvec,
                                                  float* __restrict__ out,
                                                  int layer, int to_h) {
    extern __shared__ char sm[];
    __nv_bfloat16* sAH = (__nv_bfloat16*)(sm + SM_AH);
    __nv_bfloat16* sAL = (__nv_bfloat16*)(sm + SM_AL);
    int tid = threadIdx.x, wid = tid >> 5, lane = tid & 31;
    int row0 = blockIdx.x * 64;
    float* dst = to_h ? g_h : out;

    {
        const uint4* bh = (const uint4*)g_Bh[layer];
        const uint4* bl = (const uint4*)g_Bl[layer];
        #pragma unroll
        for (int i = 0; i < 8; i++) {
            int idx = tid + i * 256;
            int n = idx >> 4, c = idx & 15;
            *(uint4*)(sm + SM_BH + n * (PAD * 2) + c * 16) = bh[idx];
            *(uint4*)(sm + SM_BL + n * (PAD * 2) + c * 16) = bl[idx];
        }
    }
    #pragma unroll
    for (int i = 0; i < 32; i++) {
        int idx = tid + i * 256;
        int r = idx >> 7, k = idx & 127;
        int gr = row0 + r;
        float a = (gr < N_NODES) ? g_agg[(size_t)gr * EMBED_DIM + k] : 0.0f;
        __nv_bfloat16 ah = __float2bfloat16(a);
        __nv_bfloat16 al = __float2bfloat16(a - __bfloat162float(ah));
        sAH[r * PAD + k] = ah;
        sAL[r * PAD + k] = al;
    }
    __syncthreads();

    int m0 = (wid & 3) * 16;
    int n_base = (wid >> 2) * 64;

    uint32_t sb = smem_u32(sm);
    uint32_t aoff = (uint32_t)((m0 + (lane & 15)) * (PAD * 2) + (lane & 16));
    uint32_t aAddrH = sb + SM_AH + aoff;
    uint32_t aAddrL = sb + SM_AL + aoff;
    uint32_t bAddrH[4], bAddrL[4];
    #pragma unroll
    for (int p = 0; p < 4; p++) {
        int n = n_base + p * 16 + (lane & 7) + ((lane >> 1) & 8);
        uint32_t boff = (uint32_t)(n * (PAD * 2) + (lane & 8) * 2);
        bAddrH[p] = sb + SM_BH + boff;
        bAddrL[p] = sb + SM_BL + boff;
    }

    float d[8][4];
    #pragma unroll
    for (int t = 0; t < 8; t++)
        #pragma unroll
        for (int q = 0; q < 4; q++) d[t][q] = 0.0f;

    #pragma unroll
    for (int kk = 0; kk < 8; kk++) {
        uint32_t kb = kk * 32;
        uint32_t ah[4], al[4], bh[4][4], bl[4][4];
        ldm_x4(ah, aAddrH + kb);
        ldm_x4(al, aAddrL + kb);
        #pragma unroll
        for (int p = 0; p < 4; p++) {
            ldm_x4(bh[p], bAddrH[p] + kb);
            ldm_x4(bl[p], bAddrL[p] + kb);
        }
        #pragma unroll
        for (int p = 0; p < 4; p++) {
            #pragma unroll
            for (int q = 0; q < 2; q++) {
                int t = p * 2 + q;
                mma_bf16(d[t], ah, bh[p][2 * q], bh[p][2 * q + 1]);
                mma_bf16(d[t], ah, bl[p][2 * q], bl[p][2 * q + 1]);
                mma_bf16(d[t], al, bh[p][2 * q], bh[p][2 * q + 1]);
            }
        }
    }

    int g = lane >> 2;
    int c2 = (lane & 3) * 2;
    int rowA = row0 + m0 + g;
    int rowB = rowA + 8;
    #pragma unroll
    for (int t = 0; t < 8; t++) {
        int col = n_base + t * 8 + c2;
        float bx = bvec[col], by = bvec[col + 1];
        if (rowA < N_NODES) {
            float2 o;
            o.x = tanhf(d[t][0] + bx);
            o.y = tanhf(d[t][1] + by);
            *(float2*)(dst + (size_t)rowA * EMBED_DIM + col) = o;
        }
        if (rowB < N_NODES) {
            float2 o;
            o.x = tanhf(d[t][2] + bx);
            o.y = tanhf(d[t][3] + by);
            *(float2*)(dst + (size_t)rowB * EMBED_DIM + col) = o;
        }
    }
}

extern "C" void kernel_launch(void* const* d_in, const int* in_sizes, int n_in,
                              void* d_out, int out_size) {
    const float* x  = (const float*)d_in[0];
    const int*   ei = (const int*)d_in[1];
    const float* W1 = (const float*)d_in[2];
    const float* b1 = (const float*)d_in[3];
    const float* W2 = (const float*)d_in[4];
    const float* b2 = (const float*)d_in[5];
    float* out = (float*)d_out;

    cudaFuncSetAttribute(k_mma_gemm,
                         cudaFuncAttributeMaxDynamicSharedMemorySize, MMA_SMEM);

    const int NT = 256;
    int blksE  = (N_EDGES + NT - 1) / NT;
    int blksND = (N_NODES * 32 + NT - 1) / NT;
    int blksG  = (N_NODES + 63) / 64;

    // CSR build (g_cnt is zero at entry: zero-init first run, self-cleaned after)
    k_hist<<<blksE, NT>>>(ei, W1, W2);        // + fused weight split/transpose
    k_blocksum<<<NBLK, NT>>>();
    k_scan_final<<<NBLK, NT>>>();
    k_fill<<<blksE, NT>>>(ei);

    float* out2 = (out_size >= 2 * N_NODES * EMBED_DIM)
                ? out + (size_t)N_NODES * EMBED_DIM : nullptr;

    // layer 1 (gather also writes the identity copy of x)
    k_gather<<<blksND, NT>>>(x, 0, out2);
    k_mma_gemm<<<blksG, NT, MMA_SMEM>>>(b1, out, 0, 1);

    // layer 2
    k_gather<<<blksND, NT>>>(x, 1, nullptr);
    k_mma_gemm<<<blksG, NT, MMA_SMEM>>>(b2, out, 1, 0);
}